// round 1
// baseline (speedup 1.0000x reference)
#include <cuda_runtime.h>
#include <math.h>

#define DIM 256
#define HID 512
#define NMAXN 100352
#define EMAXE 401408

// ---------------- scratch (device globals: allocation-free) ----------------
__device__ float g_h  [(size_t)NMAXN * DIM];
__device__ float g_agg[(size_t)NMAXN * DIM];
__device__ float g_hid[(size_t)NMAXN * HID];
__device__ int   g_deg [NMAXN];
__device__ int   g_rp  [NMAXN + 1];
__device__ int   g_cur [NMAXN];
__device__ int   g_csr [EMAXE];
__device__ int   g_cntT[NMAXN * 6];
__device__ int   g_cntD[NMAXN * 3];
__device__ int   g_bsum[600];
__device__ float g_bnsum[DIM];
__device__ float g_bnsq [DIM];
__device__ float g_scale[DIM];
__device__ float g_shift[DIM];

__device__ __forceinline__ void add4(float4& a, const float4 b) {
    a.x += b.x; a.y += b.y; a.z += b.z; a.w += b.w;
}
__device__ __forceinline__ void fma4(float4& a, float s, const float4 b) {
    a.x += s * b.x; a.y += s * b.y; a.z += s * b.z; a.w += s * b.w;
}

// ---------------- setup kernels ----------------
__global__ void k_zero_counts(int n) {
    int i = blockIdx.x * blockDim.x + threadIdx.x;
    if (i < n) {
        g_deg[i] = 0;
#pragma unroll
        for (int t = 0; t < 6; t++) g_cntT[i * 6 + t] = 0;
#pragma unroll
        for (int d = 0; d < 3; d++) g_cntD[i * 3 + d] = 0;
    }
}

__global__ void k_zero_bn() {
    int i = threadIdx.x;
    if (i < DIM) { g_bnsum[i] = 0.f; g_bnsq[i] = 0.f; }
}

__global__ void k_count(const int* __restrict__ ei, const int* __restrict__ ea, int E) {
    int e = blockIdx.x * blockDim.x + threadIdx.x;
    if (e < E) {
        int d = ei[E + e];
        atomicAdd(&g_deg[d], 1);
        int bt = ea[2 * e];
        int bd = ea[2 * e + 1];
        if ((unsigned)bt < 6u) atomicAdd(&g_cntT[d * 6 + bt], 1);
        if ((unsigned)bd < 3u) atomicAdd(&g_cntD[d * 3 + bd], 1);
    }
}

__global__ void k_scan1(int n) {
    __shared__ int s[512];
    int tid = threadIdx.x;
    int i = blockIdx.x * 512 + tid;
    int v = (i < n) ? g_deg[i] : 0;
    s[tid] = v; __syncthreads();
    for (int off = 1; off < 512; off <<= 1) {
        int t = (tid >= off) ? s[tid - off] : 0;
        __syncthreads();
        s[tid] += t;
        __syncthreads();
    }
    if (i < n) g_rp[i] = s[tid] - v;          // exclusive within block
    if (tid == 511) g_bsum[blockIdx.x] = s[511];
}

__global__ void k_scan2(int nb) {
    __shared__ int s[256];
    int tid = threadIdx.x;
    int v = (tid < nb) ? g_bsum[tid] : 0;
    s[tid] = v; __syncthreads();
    for (int off = 1; off < 256; off <<= 1) {
        int t = (tid >= off) ? s[tid - off] : 0;
        __syncthreads();
        s[tid] += t;
        __syncthreads();
    }
    if (tid < nb) g_bsum[tid] = s[tid] - v;   // exclusive block offsets
    if (tid == 0) g_bsum[nb] = s[255];        // total = E
}

__global__ void k_scan3(int n, int nb) {
    int i = blockIdx.x * 512 + threadIdx.x;
    if (i < n) {
        int r = g_rp[i] + g_bsum[blockIdx.x];
        g_rp[i] = r;
        g_cur[i] = r;
    }
    if (i == 0) g_rp[n] = g_bsum[nb];
}

__global__ void k_scatter(const int* __restrict__ ei, int E) {
    int e = blockIdx.x * blockDim.x + threadIdx.x;
    if (e < E) {
        int s = ei[e];
        int d = ei[E + e];
        int p = atomicAdd(&g_cur[d], 1);
        g_csr[p] = s;
    }
}

// ---------------- aggregation: agg = h + self_emb + counts.E + sum_{src in N(dst)} h[src] ----------------
__global__ void k_agg(const float* __restrict__ E1l, const float* __restrict__ E2l, int n) {
    __shared__ float sE[2560];  // [0,1536) E1 (6x256), [1536,2304) E2 (3x256), [2304,2560) self
    int tid = threadIdx.x;
    for (int i = tid; i < 1536; i += 256) sE[i] = E1l[i];
    for (int i = tid; i < 768; i += 256) sE[1536 + i] = E2l[i];
    __syncthreads();
    if (tid < 256) sE[2304 + tid] = sE[4 * 256 + tid] + sE[1536 + tid];  // E1[4] + E2[0]
    __syncthreads();

    int node = blockIdx.x * 8 + (tid >> 5);
    if (node >= n) return;
    int lane = tid & 31;
    int c0 = lane * 4, c1 = 128 + lane * 4;

    const float* hr = g_h + (size_t)node * DIM;
    float4 a0 = *(const float4*)(hr + c0);
    float4 a1 = *(const float4*)(hr + c1);
    add4(a0, *(const float4*)(sE + 2304 + c0));
    add4(a1, *(const float4*)(sE + 2304 + c1));
#pragma unroll
    for (int t = 0; t < 6; t++) {
        int ct = g_cntT[node * 6 + t];
        if (ct) {
            float f = (float)ct;
            fma4(a0, f, *(const float4*)(sE + t * 256 + c0));
            fma4(a1, f, *(const float4*)(sE + t * 256 + c1));
        }
    }
#pragma unroll
    for (int d = 0; d < 3; d++) {
        int cd = g_cntD[node * 3 + d];
        if (cd) {
            float f = (float)cd;
            fma4(a0, f, *(const float4*)(sE + 1536 + d * 256 + c0));
            fma4(a1, f, *(const float4*)(sE + 1536 + d * 256 + c1));
        }
    }
    int e0 = g_rp[node], e1 = g_rp[node + 1];
    for (int e = e0; e < e1; e++) {
        const float* hs = g_h + (size_t)g_csr[e] * DIM;
        add4(a0, *(const float4*)(hs + c0));
        add4(a1, *(const float4*)(hs + c1));
    }
    float* ar = g_agg + (size_t)node * DIM;
    *(float4*)(ar + c0) = a0;
    *(float4*)(ar + c1) = a1;
}

// ---------------- SGEMM: C[M,N] = A[M,K] @ B[K,N] + bias, EPI 1=relu, 2=store+BN stats ----------------
template <int EPI>
__global__ void __launch_bounds__(256) k_sgemm(
    const float* __restrict__ A, const float* __restrict__ B,
    const float* __restrict__ bias, float* __restrict__ C,
    int M, int K, int N)
{
    __shared__ float As[2][16][128];
    __shared__ float Bs[2][16][128];
    __shared__ float ssum[128], ssq[128];
    int tid = threadIdx.x;
    int ty = tid >> 4, tx = tid & 15;
    int rowBase = blockIdx.y * 128, colBase = blockIdx.x * 128;
    float acc[8][8];
#pragma unroll
    for (int i = 0; i < 8; i++)
#pragma unroll
        for (int j = 0; j < 8; j++) acc[i][j] = 0.f;

    int aRow = tid >> 2, aK4 = (tid & 3) * 4;
    int bK = tid >> 5, bC = (tid & 31) * 4;
    const int nk = K >> 4;

    // prologue: tile 0 -> buf 0
    {
#pragma unroll
        for (int i = 0; i < 2; i++) {
            int r = aRow + i * 64;
            int gr = min(rowBase + r, M - 1);
            float4 v = *(const float4*)(A + (size_t)gr * K + aK4);
            As[0][aK4 + 0][r] = v.x; As[0][aK4 + 1][r] = v.y;
            As[0][aK4 + 2][r] = v.z; As[0][aK4 + 3][r] = v.w;
        }
#pragma unroll
        for (int i = 0; i < 2; i++) {
            int kr = bK + i * 8;
            *(float4*)&Bs[0][kr][bC] = *(const float4*)(B + (size_t)kr * N + colBase + bC);
        }
    }
    __syncthreads();

    for (int kt = 0; kt < nk; kt++) {
        int buf = kt & 1;
        if (kt + 1 < nk) {
            int k0 = (kt + 1) << 4;
#pragma unroll
            for (int i = 0; i < 2; i++) {
                int r = aRow + i * 64;
                int gr = min(rowBase + r, M - 1);
                float4 v = *(const float4*)(A + (size_t)gr * K + k0 + aK4);
                As[buf ^ 1][aK4 + 0][r] = v.x; As[buf ^ 1][aK4 + 1][r] = v.y;
                As[buf ^ 1][aK4 + 2][r] = v.z; As[buf ^ 1][aK4 + 3][r] = v.w;
            }
#pragma unroll
            for (int i = 0; i < 2; i++) {
                int kr = bK + i * 8;
                *(float4*)&Bs[buf ^ 1][kr][bC] =
                    *(const float4*)(B + (size_t)(k0 + kr) * N + colBase + bC);
            }
        }
#pragma unroll
        for (int k = 0; k < 16; k++) {
            float a[8], b[8];
            *(float4*)&a[0] = *(const float4*)&As[buf][k][ty * 8];
            *(float4*)&a[4] = *(const float4*)&As[buf][k][ty * 8 + 4];
            *(float4*)&b[0] = *(const float4*)&Bs[buf][k][tx * 8];
            *(float4*)&b[4] = *(const float4*)&Bs[buf][k][tx * 8 + 4];
#pragma unroll
            for (int i = 0; i < 8; i++)
#pragma unroll
                for (int j = 0; j < 8; j++)
                    acc[i][j] += a[i] * b[j];
        }
        __syncthreads();
    }

    // epilogue
    float bv[8];
    *(float4*)&bv[0] = *(const float4*)(bias + colBase + tx * 8);
    *(float4*)&bv[4] = *(const float4*)(bias + colBase + tx * 8 + 4);

    float csum[8], csq[8];
    if (EPI == 2) {
#pragma unroll
        for (int j = 0; j < 8; j++) { csum[j] = 0.f; csq[j] = 0.f; }
        if (tid < 128) { ssum[tid] = 0.f; ssq[tid] = 0.f; }
        __syncthreads();
    }

#pragma unroll
    for (int i = 0; i < 8; i++) {
        int r = rowBase + ty * 8 + i;
        bool ok = r < M;
        float vals[8];
#pragma unroll
        for (int j = 0; j < 8; j++) {
            float v = acc[i][j] + bv[j];
            if (EPI == 1) v = fmaxf(v, 0.f);
            vals[j] = v;
            if (EPI == 2) { if (ok) { csum[j] += v; csq[j] += v * v; } }
        }
        if (ok) {
            float* cp = C + (size_t)r * N + colBase + tx * 8;
            *(float4*)cp = *(float4*)&vals[0];
            *(float4*)(cp + 4) = *(float4*)&vals[4];
        }
    }

    if (EPI == 2) {
#pragma unroll
        for (int j = 0; j < 8; j++) {
            atomicAdd(&ssum[tx * 8 + j], csum[j]);
            atomicAdd(&ssq[tx * 8 + j], csq[j]);
        }
        __syncthreads();
        if (tid < 128) {
            atomicAdd(&g_bnsum[colBase + tid], ssum[tid]);
            atomicAdd(&g_bnsq[colBase + tid], ssq[tid]);
        }
    }
}

// ---------------- batch norm ----------------
__global__ void k_bnfin(const float* __restrict__ gamma, const float* __restrict__ beta, float invN) {
    int c = threadIdx.x;
    float m = g_bnsum[c] * invN;
    float var = g_bnsq[c] * invN - m * m;
    float sc = gamma[c] * rsqrtf(var + 1e-5f);
    g_scale[c] = sc;
    g_shift[c] = beta[c] - m * sc;
}

__global__ void k_bnapply(float* __restrict__ dst, int n) {
    int i = blockIdx.x * blockDim.x + threadIdx.x;
    int tot = n * 64;
    if (i < tot) {
        int c4 = (i & 63) * 4;
        float4 v = *((const float4*)g_agg + i);
        v.x = v.x * g_scale[c4 + 0] + g_shift[c4 + 0];
        v.y = v.y * g_scale[c4 + 1] + g_shift[c4 + 1];
        v.z = v.z * g_scale[c4 + 2] + g_shift[c4 + 2];
        v.w = v.w * g_scale[c4 + 3] + g_shift[c4 + 3];
        *((float4*)dst + i) = v;
    }
}

// ---------------- launch ----------------
extern "C" void kernel_launch(void* const* d_in, const int* in_sizes, int n_in,
                              void* d_out, int out_size) {
    const float* x     = (const float*)d_in[0];
    const int*   ei    = (const int*)  d_in[1];
    const int*   ea    = (const int*)  d_in[2];
    const float* Wl    = (const float*)d_in[3];
    const float* bl    = (const float*)d_in[4];
    const float* W1    = (const float*)d_in[5];
    const float* b1    = (const float*)d_in[6];
    const float* W2    = (const float*)d_in[7];
    const float* b2    = (const float*)d_in[8];
    const float* E1    = (const float*)d_in[9];
    const float* E2    = (const float*)d_in[10];
    const float* gamma = (const float*)d_in[11];
    const float* beta  = (const float*)d_in[12];

    int N = in_sizes[0] / 128;   // 100000 nodes
    int E = in_sizes[1] / 2;     // 400000 edges

    float *p_h, *p_agg, *p_hid;
    cudaGetSymbolAddress((void**)&p_h,   g_h);
    cudaGetSymbolAddress((void**)&p_agg, g_agg);
    cudaGetSymbolAddress((void**)&p_hid, g_hid);

    int nb512 = (N + 511) / 512;

    // CSR + per-node edge-type counts (layer-invariant)
    k_zero_counts<<<(N + 255) / 256, 256>>>(N);
    k_count<<<(E + 255) / 256, 256>>>(ei, ea, E);
    k_scan1<<<nb512, 512>>>(N);
    k_scan2<<<1, 256>>>(nb512);
    k_scan3<<<nb512, 512>>>(N, nb512);
    k_scatter<<<(E + 255) / 256, 256>>>(ei, E);

    int my = (N + 127) / 128;

    // h = relu(x @ Wl + bl)
    k_sgemm<1><<<dim3(2, my), 256>>>(x, Wl, bl, p_h, N, 128, 256);

    float invN = 1.f / (float)N;
    for (int l = 0; l < 5; l++) {
        k_agg<<<(N + 7) / 8, 256>>>(E1 + (size_t)l * 6 * DIM, E2 + (size_t)l * 3 * DIM, N);
        k_sgemm<1><<<dim3(4, my), 256>>>(p_agg, W1 + (size_t)l * DIM * HID,
                                         b1 + (size_t)l * HID, p_hid, N, DIM, HID);
        k_zero_bn<<<1, 256>>>();
        k_sgemm<2><<<dim3(2, my), 256>>>(p_hid, W2 + (size_t)l * HID * DIM,
                                         b2 + (size_t)l * DIM, p_agg, N, HID, DIM);
        k_bnfin<<<1, 256>>>(gamma + (size_t)l * DIM, beta + (size_t)l * DIM, invN);
        float* dst = (l == 4) ? (float*)d_out : p_h;
        k_bnapply<<<(N * 64 + 255) / 256, 256>>>(dst, N);
    }
}